// round 7
// baseline (speedup 1.0000x reference)
#include <cuda_runtime.h>
#include <cuda_fp16.h>
#include <cstdint>

// ---------------------------------------------------------------------------
// V0 = pt @ (U0 * s1)^T, V1 = pt @ (U1 * s0)^T;  s_i = colsum(U_i), K = 32.
// fp16 mma.sync, asymmetric split: A = ah + al, B rounded; C = ah@bh + al@bh.
// Fused launch, tile 128x64, warp tile 32x32.
// R6: smem-staged coalesced epilogue (STG.128) + hoisted B fragments.
// ---------------------------------------------------------------------------

#define R_DIM 32
#define BM 128
#define BN 64
#define LDA 72     // A smem row stride in halves (144 B)
#define LDB 40     // B smem row stride in halves (80 B)
#define LDC 72     // epilogue staging row stride in floats (288 B)

__device__ float g_s[2][R_DIM];

__device__ __forceinline__ uint32_t smem_u32(const void* p) {
    uint32_t a;
    asm("{ .reg .u64 t; cvta.to.shared.u64 t, %1; cvt.u32.u64 %0, t; }"
        : "=r"(a) : "l"(p));
    return a;
}

__device__ __forceinline__ void ldsm_x4(uint32_t addr, uint32_t r[4]) {
    asm volatile("ldmatrix.sync.aligned.m8n8.x4.shared.b16 {%0,%1,%2,%3}, [%4];"
                 : "=r"(r[0]), "=r"(r[1]), "=r"(r[2]), "=r"(r[3]) : "r"(addr));
}

__device__ __forceinline__ void mma_16816(float c[4], const uint32_t a[4],
                                          uint32_t b0, uint32_t b1) {
    asm volatile(
        "mma.sync.aligned.m16n8k16.row.col.f32.f16.f16.f32 "
        "{%0,%1,%2,%3}, {%4,%5,%6,%7}, {%8,%9}, {%0,%1,%2,%3};"
        : "+f"(c[0]), "+f"(c[1]), "+f"(c[2]), "+f"(c[3])
        : "r"(a[0]), "r"(a[1]), "r"(a[2]), "r"(a[3]), "r"(b0), "r"(b1));
}

__device__ __forceinline__ void stg_cs_v4(float* p, float4 v) {
    asm volatile("st.global.cs.v4.f32 [%0], {%1,%2,%3,%4};"
                 :: "l"(p), "f"(v.x), "f"(v.y), "f"(v.z), "f"(v.w) : "memory");
}

__device__ __forceinline__ uint64_t split4h(float4 v, uint64_t& lo_out) {
    __half h0 = __float2half_rn(v.x), h1 = __float2half_rn(v.y);
    __half h2 = __float2half_rn(v.z), h3 = __float2half_rn(v.w);
    __half l0 = __float2half_rn(v.x - __half2float(h0));
    __half l1 = __float2half_rn(v.y - __half2float(h1));
    __half l2 = __float2half_rn(v.z - __half2float(h2));
    __half l3 = __float2half_rn(v.w - __half2float(h3));
    union { __half h[4]; uint64_t u; } ph, pl;
    ph.h[0] = h0; ph.h[1] = h1; ph.h[2] = h2; ph.h[3] = h3;
    pl.h[0] = l0; pl.h[1] = l1; pl.h[2] = l2; pl.h[3] = l3;
    lo_out = pl.u;
    return ph.u;
}
__device__ __forceinline__ uint64_t round4h(float4 v) {
    union { __half h[4]; uint64_t u; } p;
    p.h[0] = __float2half_rn(v.x); p.h[1] = __float2half_rn(v.y);
    p.h[2] = __float2half_rn(v.z); p.h[3] = __float2half_rn(v.w);
    return p.u;
}

// ---------------------------------------------------------------------------
__global__ __launch_bounds__(1024)
void colsum_kernel(const float* __restrict__ U0, int n0,
                   const float* __restrict__ U1, int n1) {
    const float* U = (blockIdx.x == 0) ? U0 : U1;
    const int n    = (blockIdx.x == 0) ? n0 : n1;

    __shared__ float part[128][R_DIM];
    const int t = threadIdx.x;
    const int c4 = (t & 7) * 4;
    const int grp = t >> 3;

    float4 acc = make_float4(0.f, 0.f, 0.f, 0.f);
    #pragma unroll 4
    for (int r = grp; r < n; r += 128) {
        float4 v = *(const float4*)(U + (size_t)r * R_DIM + c4);
        acc.x += v.x; acc.y += v.y; acc.z += v.z; acc.w += v.w;
    }
    part[grp][c4 + 0] = acc.x;
    part[grp][c4 + 1] = acc.y;
    part[grp][c4 + 2] = acc.z;
    part[grp][c4 + 3] = acc.w;
    __syncthreads();

    if (t < R_DIM) {
        float s = 0.0f;
        #pragma unroll 16
        for (int g = 0; g < 128; ++g) s += part[g][t];
        g_s[blockIdx.x][t] = s;
    }
}

// ---------------------------------------------------------------------------
__global__ __launch_bounds__(256)
void mma_gemm_kernel(const float* __restrict__ A,
                     const float* __restrict__ B0,
                     const float* __restrict__ B1,
                     float* __restrict__ C_all,
                     int P, int N0, int N1, int T0, int NT0, int NT1) {
    __shared__ __align__(16) __half sA[BM * LDA];   // 18432 B (= 64*72 floats)
    __shared__ __align__(16) __half sB[BN * LDB];   //  5120 B

    const uint32_t s_a = smem_u32(sA);
    const uint32_t s_b = smem_u32(sB);

    int bid = blockIdx.x;
    const float* B;
    float* C;
    int N, s_idx, nt, mt;
    if (bid < T0) {
        B = B0; C = C_all; N = N0; s_idx = 1;
        nt = bid % NT0; mt = bid / NT0;
    } else {
        bid -= T0;
        B = B1; C = C_all + (size_t)P * N0; N = N1; s_idx = 0;
        nt = bid % NT1; mt = bid / NT1;
    }
    const int m0 = mt * BM;
    const int n0 = nt * BN;

    const int tid  = threadIdx.x;
    const int wid  = tid >> 5;
    const int lane = tid & 31;

    // ---- fill A tile (hi | lo halves per row) ----
    #pragma unroll
    for (int i = 0; i < 4; ++i) {
        int idx = i * 256 + tid;
        int r = idx >> 3, q = idx & 7;
        int row = m0 + r;
        float4 v = make_float4(0.f, 0.f, 0.f, 0.f);
        if (row < P) v = *(const float4*)(A + (size_t)row * R_DIM + q * 4);
        uint64_t lo, hi = split4h(v, lo);
        uint32_t base = r * (LDA * 2) + q * 8;
        asm volatile("st.shared.b64 [%0], %1;" :: "r"(s_a + base), "l"(hi) : "memory");
        asm volatile("st.shared.b64 [%0], %1;" :: "r"(s_a + base + 64), "l"(lo) : "memory");
    }

    // ---- fill B tile (scale fused, fp16-rounded) ----
    const float* __restrict__ sv = g_s[s_idx];
    #pragma unroll
    for (int i = 0; i < 2; ++i) {
        int idx = i * 256 + tid;
        int r = idx >> 3, q = idx & 7;
        int nn = n0 + r;
        float4 v = make_float4(0.f, 0.f, 0.f, 0.f);
        if (nn < N) {
            v = *(const float4*)(B + (size_t)nn * R_DIM + q * 4);
            v.x *= sv[q * 4 + 0]; v.y *= sv[q * 4 + 1];
            v.z *= sv[q * 4 + 2]; v.w *= sv[q * 4 + 3];
        }
        uint64_t hb = round4h(v);
        uint32_t base = r * (LDB * 2) + q * 8;
        asm volatile("st.shared.b64 [%0], %1;" :: "r"(s_b + base), "l"(hb) : "memory");
    }
    __syncthreads();

    const int m_w = (wid >> 1) * 32;
    const int n_w = (wid & 1) * 32;

    float acc[2][4][4];
    #pragma unroll
    for (int fm = 0; fm < 2; ++fm)
        #pragma unroll
        for (int fn = 0; fn < 4; ++fn)
            #pragma unroll
            for (int j = 0; j < 4; ++j) acc[fm][fn][j] = 0.f;

    const uint32_t a_row  = m_w + (lane & 15);
    const uint32_t a_koff = (lane >> 4) * 8;
    const uint32_t b_row  = n_w + (lane >> 4) * 8 + (lane & 7);
    const uint32_t b_koff = ((lane >> 3) & 1) * 8;

    const uint32_t a_base = s_a + a_row * (LDA * 2) + a_koff * 2;
    const uint32_t b_base = s_b + b_row * (LDB * 2) + b_koff * 2;

    // ---- mainloop: B k-steps {0,1}, each reused by hh (ak=kb) and lh (ak=kb+2)
    #pragma unroll
    for (int kb = 0; kb < 2; ++kb) {
        uint32_t bfrag[4][2];
        #pragma unroll
        for (int f2 = 0; f2 < 2; ++f2) {
            uint32_t r[4];
            ldsm_x4(b_base + f2 * 16 * (LDB * 2) + kb * 32, r);
            bfrag[f2 * 2 + 0][0] = r[0]; bfrag[f2 * 2 + 0][1] = r[1];
            bfrag[f2 * 2 + 1][0] = r[2]; bfrag[f2 * 2 + 1][1] = r[3];
        }
        #pragma unroll
        for (int half = 0; half < 2; ++half) {
            const int ak = kb + half * 2;
            uint32_t afrag[2][4];
            #pragma unroll
            for (int fm = 0; fm < 2; ++fm)
                ldsm_x4(a_base + fm * 16 * (LDA * 2) + ak * 32, afrag[fm]);
            #pragma unroll
            for (int fm = 0; fm < 2; ++fm)
                #pragma unroll
                for (int fn = 0; fn < 4; ++fn)
                    mma_16816(acc[fm][fn], afrag[fm], bfrag[fn][0], bfrag[fn][1]);
        }
    }

    // ---- staged epilogue: reuse sA as 64x72 fp32 buffer, 2 passes (fm) ----
    __syncthreads();                       // all LDSM done before overwrite
    float* stage = reinterpret_cast<float*>(sA);
    const int g  = lane >> 2;
    const int tg = lane & 3;

    #pragma unroll
    for (int fm = 0; fm < 2; ++fm) {
        // scatter fragments into smem (rows 0..63 = 4 warp-m-groups x 16)
        #pragma unroll
        for (int h8 = 0; h8 < 2; ++h8) {
            int srow = (wid >> 1) * 16 + g + h8 * 8;
            float* sp = stage + srow * LDC + n_w + tg * 2;
            #pragma unroll
            for (int fn = 0; fn < 4; ++fn) {
                float2 v = h8 ? make_float2(acc[fm][fn][2], acc[fm][fn][3])
                              : make_float2(acc[fm][fn][0], acc[fm][fn][1]);
                *(float2*)(sp + fn * 8) = v;
            }
        }
        __syncthreads();
        // coalesced stores: 64 rows x 64 cols, float4 per thread
        #pragma unroll
        for (int i = 0; i < 4; ++i) {
            int srow = i * 16 + (tid >> 4);
            int col  = (tid & 15) * 4;
            int gr = m0 + (srow >> 4) * 32 + fm * 16 + (srow & 15);
            int gc = n0 + col;
            if (gr < P && gc < N) {        // N % 4 == 0 -> float4 all-or-nothing
                float4 v = *(float4*)(stage + srow * LDC + col);
                stg_cs_v4(C + (size_t)gr * N + gc, v);
            }
        }
        __syncthreads();
    }
}

// ---------------------------------------------------------------------------
extern "C" void kernel_launch(void* const* d_in, const int* in_sizes, int n_in,
                              void* d_out, int out_size) {
    const float* pt = (const float*)d_in[0];
    const float* U0 = (const float*)d_in[1];
    const float* U1 = (const float*)d_in[2];
    float* out = (float*)d_out;

    const int P  = in_sizes[0] / R_DIM;
    const int N0 = in_sizes[1] / R_DIM;
    const int N1 = in_sizes[2] / R_DIM;

    colsum_kernel<<<2, 1024>>>(U0, N0, U1, N1);

    const int MT  = (P + BM - 1) / BM;
    const int NT0 = (N0 + BN - 1) / BN;
    const int NT1 = (N1 + BN - 1) / BN;
    const int T0  = MT * NT0;
    const int T1  = MT * NT1;

    mma_gemm_kernel<<<T0 + T1, 256>>>(pt, U0, U1, out, P, N0, N1, T0, NT0, NT1);
}

// round 9
// speedup vs baseline: 1.3423x; 1.3423x over previous
#include <cuda_runtime.h>
#include <cuda_fp16.h>
#include <cstdint>

// ---------------------------------------------------------------------------
// V0 = pt @ (U0 * s1)^T, V1 = pt @ (U1 * s0)^T;  s_i = colsum(U_i), K = 32.
// fp16 mma.sync, asymmetric split: A = ah + al, B rounded; C = ah@bh + al@bh.
// R7: persistent m-band CTAs. A band filled once; loop over CH n-tiles with
// double-buffered, register-prefetched B. Direct streaming epilogue (R5).
// ---------------------------------------------------------------------------

#define R_DIM 32
#define BM 128
#define BN 64
#define LDA 72     // A smem row stride in halves (144 B)
#define LDB 40     // B smem row stride in halves (80 B)
#define CH  8      // n-tiles per CTA

__device__ float g_s[2][R_DIM];   // g_s[0]=colsum(U0), g_s[1]=colsum(U1)

__device__ __forceinline__ uint32_t smem_u32(const void* p) {
    uint32_t a;
    asm("{ .reg .u64 t; cvta.to.shared.u64 t, %1; cvt.u32.u64 %0, t; }"
        : "=r"(a) : "l"(p));
    return a;
}

__device__ __forceinline__ void ldsm_x4(uint32_t addr, uint32_t r[4]) {
    asm volatile("ldmatrix.sync.aligned.m8n8.x4.shared.b16 {%0,%1,%2,%3}, [%4];"
                 : "=r"(r[0]), "=r"(r[1]), "=r"(r[2]), "=r"(r[3]) : "r"(addr));
}

__device__ __forceinline__ void mma_16816(float c[4], const uint32_t a[4],
                                          uint32_t b0, uint32_t b1) {
    asm volatile(
        "mma.sync.aligned.m16n8k16.row.col.f32.f16.f16.f32 "
        "{%0,%1,%2,%3}, {%4,%5,%6,%7}, {%8,%9}, {%0,%1,%2,%3};"
        : "+f"(c[0]), "+f"(c[1]), "+f"(c[2]), "+f"(c[3])
        : "r"(a[0]), "r"(a[1]), "r"(a[2]), "r"(a[3]), "r"(b0), "r"(b1));
}

__device__ __forceinline__ void stg_cs_v2(float* p, float x, float y) {
    asm volatile("st.global.cs.v2.f32 [%0], {%1,%2};" :: "l"(p), "f"(x), "f"(y)
                 : "memory");
}

__device__ __forceinline__ uint64_t split4h(float4 v, uint64_t& lo_out) {
    __half h0 = __float2half_rn(v.x), h1 = __float2half_rn(v.y);
    __half h2 = __float2half_rn(v.z), h3 = __float2half_rn(v.w);
    __half l0 = __float2half_rn(v.x - __half2float(h0));
    __half l1 = __float2half_rn(v.y - __half2float(h1));
    __half l2 = __float2half_rn(v.z - __half2float(h2));
    __half l3 = __float2half_rn(v.w - __half2float(h3));
    union { __half h[4]; uint64_t u; } ph, pl;
    ph.h[0] = h0; ph.h[1] = h1; ph.h[2] = h2; ph.h[3] = h3;
    pl.h[0] = l0; pl.h[1] = l1; pl.h[2] = l2; pl.h[3] = l3;
    lo_out = pl.u;
    return ph.u;
}
__device__ __forceinline__ uint64_t round4h(float4 v) {
    union { __half h[4]; uint64_t u; } p;
    p.h[0] = __float2half_rn(v.x); p.h[1] = __float2half_rn(v.y);
    p.h[2] = __float2half_rn(v.z); p.h[3] = __float2half_rn(v.w);
    return p.u;
}

// ---------------------------------------------------------------------------
__global__ __launch_bounds__(1024)
void colsum_kernel(const float* __restrict__ U0, int n0,
                   const float* __restrict__ U1, int n1) {
    const float* U = (blockIdx.x == 0) ? U0 : U1;
    const int n    = (blockIdx.x == 0) ? n0 : n1;

    __shared__ float part[128][R_DIM];
    const int t = threadIdx.x;
    const int c4 = (t & 7) * 4;
    const int grp = t >> 3;

    float4 acc = make_float4(0.f, 0.f, 0.f, 0.f);
    #pragma unroll 4
    for (int r = grp; r < n; r += 128) {
        float4 v = *(const float4*)(U + (size_t)r * R_DIM + c4);
        acc.x += v.x; acc.y += v.y; acc.z += v.z; acc.w += v.w;
    }
    part[grp][c4 + 0] = acc.x;
    part[grp][c4 + 1] = acc.y;
    part[grp][c4 + 2] = acc.z;
    part[grp][c4 + 3] = acc.w;
    __syncthreads();

    if (t < R_DIM) {
        float s = 0.0f;
        #pragma unroll 16
        for (int g = 0; g < 128; ++g) s += part[g][t];
        g_s[blockIdx.x][t] = s;
    }
}

// ---------------------------------------------------------------------------
// Persistent m-band GEMM.  blockIdx.y = m-band, blockIdx.x = n-tile chunk.
// Flat n-tile index nt in [0, NT0+NT1): nt < NT0 -> output 0, else output 1.
// ---------------------------------------------------------------------------
__global__ __launch_bounds__(256)
void mma_gemm_kernel(const float* __restrict__ A,
                     const float* __restrict__ B0,
                     const float* __restrict__ B1,
                     float* __restrict__ C_all,
                     int P, int N0, int N1, int NT0, int NT) {
    __shared__ __align__(16) __half sA[BM * LDA];        // 18432 B
    __shared__ __align__(16) __half sB[2][BN * LDB];     // 2 x 5120 B

    const uint32_t s_a = smem_u32(sA);

    const int tid  = threadIdx.x;
    const int wid  = tid >> 5;
    const int lane = tid & 31;
    const int m0   = blockIdx.y * BM;
    const int nt0  = blockIdx.x * CH;
    if (nt0 >= NT) return;

    // ---- fill A band once (hi | lo halves per row) ----
    #pragma unroll
    for (int i = 0; i < 4; ++i) {
        int idx = i * 256 + tid;
        int r = idx >> 3, q = idx & 7;
        int row = m0 + r;
        float4 v = make_float4(0.f, 0.f, 0.f, 0.f);
        if (row < P) v = *(const float4*)(A + (size_t)row * R_DIM + q * 4);
        uint64_t lo, hi = split4h(v, lo);
        uint32_t base = r * (LDA * 2) + q * 8;
        asm volatile("st.shared.b64 [%0], %1;" :: "r"(s_a + base), "l"(hi) : "memory");
        asm volatile("st.shared.b64 [%0], %1;" :: "r"(s_a + base + 64), "l"(lo) : "memory");
    }

    // per-thread B fill coordinates (same quad q for both halves)
    const int b_q  = tid & 7;
    const int b_r0 = tid >> 3;          // rows b_r0 and b_r0+32

    // ---- prefetch helper: scale + fp16-round at load, 2 x u64 regs ----
    uint64_t pf[2];
    auto prefetch_b = [&](int nt) {
        const float* Bp; int N, n0c, s_idx;
        if (nt < NT0) { Bp = B0; N = N0; n0c = nt * BN; s_idx = 1; }
        else          { Bp = B1; N = N1; n0c = (nt - NT0) * BN; s_idx = 0; }
        float4 sv = *(const float4*)(g_s[s_idx] + b_q * 4);
        #pragma unroll
        for (int j = 0; j < 2; ++j) {
            int nn = n0c + b_r0 + j * 32;
            float4 v = make_float4(0.f, 0.f, 0.f, 0.f);
            if (nn < N) {
                v = *(const float4*)(Bp + (size_t)nn * R_DIM + b_q * 4);
                v.x *= sv.x; v.y *= sv.y; v.z *= sv.z; v.w *= sv.w;
            }
            pf[j] = round4h(v);
        }
    };

    prefetch_b(nt0);

    // fragment addressing (fixed per thread)
    const int m_w = (wid >> 1) * 32;
    const int n_w = (wid & 1) * 32;
    const uint32_t a_row  = m_w + (lane & 15);
    const uint32_t a_koff = (lane >> 4) * 8;
    const uint32_t b_row  = n_w + (lane >> 4) * 8 + (lane & 7);
    const uint32_t b_koff = ((lane >> 3) & 1) * 8;
    const uint32_t a_base = s_a + a_row * (LDA * 2) + a_koff * 2;

    const int g  = lane >> 2;
    const int tg = lane & 3;

    // ---- n-tile loop ----
    for (int i = 0; i < CH; ++i) {
        const int nt = nt0 + i;
        if (nt >= NT) break;

        float* C; int N, n0c;
        if (nt < NT0) { C = C_all; N = N0; n0c = nt * BN; }
        else { C = C_all + (size_t)P * N0; N = N1; n0c = (nt - NT0) * BN; }

        // commit prefetched B into buffer i&1
        const uint32_t s_b = smem_u32(sB[i & 1]);
        #pragma unroll
        for (int j = 0; j < 2; ++j) {
            uint32_t base = (b_r0 + j * 32) * (LDB * 2) + b_q * 8;
            asm volatile("st.shared.b64 [%0], %1;" :: "r"(s_b + base), "l"(pf[j])
                         : "memory");
        }
        __syncthreads();

        // kick off next tile's B loads (latency hidden by mainloop+epilogue)
        if (i + 1 < CH && nt + 1 < NT) prefetch_b(nt + 1);

        // ---- mainloop: B k-steps {0,1}, each reused by hh & lh ----
        float acc[2][4][4];
        #pragma unroll
        for (int fm = 0; fm < 2; ++fm)
            #pragma unroll
            for (int fn = 0; fn < 4; ++fn)
                #pragma unroll
                for (int j = 0; j < 4; ++j) acc[fm][fn][j] = 0.f;

        const uint32_t b_base = s_b + b_row * (LDB * 2) + b_koff * 2;
        #pragma unroll
        for (int kb = 0; kb < 2; ++kb) {
            uint32_t bfrag[4][2];
            #pragma unroll
            for (int f2 = 0; f2 < 2; ++f2) {
                uint32_t r[4];
                ldsm_x4(b_base + f2 * 16 * (LDB * 2) + kb * 32, r);
                bfrag[f2 * 2 + 0][0] = r[0]; bfrag[f2 * 2 + 0][1] = r[1];
                bfrag[f2 * 2 + 1][0] = r[2]; bfrag[f2 * 2 + 1][1] = r[3];
            }
            #pragma unroll
            for (int half = 0; half < 2; ++half) {
                const int ak = kb + half * 2;
                uint32_t afrag[2][4];
                #pragma unroll
                for (int fm = 0; fm < 2; ++fm)
                    ldsm_x4(a_base + fm * 16 * (LDA * 2) + ak * 32, afrag[fm]);
                #pragma unroll
                for (int fm = 0; fm < 2; ++fm)
                    #pragma unroll
                    for (int fn = 0; fn < 4; ++fn)
                        mma_16816(acc[fm][fn], afrag[fm], bfrag[fn][0], bfrag[fn][1]);
            }
        }

        // ---- direct streaming epilogue (R5 layout) ----
        #pragma unroll
        for (int fm = 0; fm < 2; ++fm) {
            #pragma unroll
            for (int fn = 0; fn < 4; ++fn) {
                int col = n0c + n_w + fn * 8 + tg * 2;
                if (col < N) {
                    int r0 = m0 + m_w + fm * 16 + g;
                    int r1 = r0 + 8;
                    if (r0 < P) stg_cs_v2(C + (size_t)r0 * N + col,
                                          acc[fm][fn][0], acc[fm][fn][1]);
                    if (r1 < P) stg_cs_v2(C + (size_t)r1 * N + col,
                                          acc[fm][fn][2], acc[fm][fn][3]);
                }
            }
        }
        // next iteration's STS targets the other buffer; the sync at its top
        // orders it against this tile's ldsm reads.
    }
}

// ---------------------------------------------------------------------------
extern "C" void kernel_launch(void* const* d_in, const int* in_sizes, int n_in,
                              void* d_out, int out_size) {
    const float* pt = (const float*)d_in[0];
    const float* U0 = (const float*)d_in[1];
    const float* U1 = (const float*)d_in[2];
    float* out = (float*)d_out;

    const int P  = in_sizes[0] / R_DIM;
    const int N0 = in_sizes[1] / R_DIM;
    const int N1 = in_sizes[2] / R_DIM;

    colsum_kernel<<<2, 1024>>>(U0, N0, U1, N1);

    const int MT  = (P + BM - 1) / BM;
    const int NT0 = (N0 + BN - 1) / BN;
    const int NT1 = (N1 + BN - 1) / BN;
    const int NT  = NT0 + NT1;
    const int NCH = (NT + CH - 1) / CH;

    dim3 grid(NCH, MT);
    mma_gemm_kernel<<<grid, 256>>>(pt, U0, U1, out, P, N0, N1, NT0, NT);
}